// round 5
// baseline (speedup 1.0000x reference)
#include <cuda_runtime.h>

#define BB_   64
#define DIN_  512
#define HH_   512

#define GEMM_BLOCKS  32
#define TOTAL_BLOCKS 592        // 148 SMs * 4 blocks -> single wave
#define NTHREADS     256

#define CHUNK_V      2048       // float4 per chunk (16 * 128 h-vectors)
#define NV           (BB_ * DIN_ * HH_ / 4)       // 4,194,304 float4 per tensor
#define NCHUNK       (2 * (NV / CHUNK_V))         // 4096 chunks (2 halves)

__device__ int g_ctr  = 0;
__device__ int g_done = 0;

__global__ void __launch_bounds__(NTHREADS, 4)
fused_kernel(const float* __restrict__ x_t,
             const float* __restrict__ h_c1,
             const float* __restrict__ h_c2,
             const float* __restrict__ gm0,
             const float* __restrict__ gm1,
             const float* __restrict__ gm2,
             const float* __restrict__ gm3,
             const float4* __restrict__ gm4,
             const float4* __restrict__ gm5,
             const float4* __restrict__ gm6,
             const float4* __restrict__ gm7,
             const float* __restrict__ r_param,
             const float* __restrict__ theta_param,
             const float* __restrict__ wx1,
             const float* __restrict__ wx2,
             float* __restrict__ out) {
    __shared__ __align__(16) float sh[4 * DIN_];   // GEMM staging
    __shared__ int s_chunk;

    const int tid = threadIdx.x;
    const int SZ_SMALL = BB_ * HH_;            // 32768
    const int SMALL    = 6 * SZ_SMALL;         // 196608 floats
    const int SZ_BIG   = BB_ * DIN_ * HH_;     // 16777216 floats

    // ================= GEMM + small epilogue (blocks 0..31) =================
    if (blockIdx.x < GEMM_BLOCKS) {
        const int BT = 4;
        const int bt = blockIdx.x >> 1;
        const int ht = blockIdx.x & 1;
        const int b0 = bt * BT;
        const int h  = ht * 256 + tid;

        float (*sx)[DIN_] = reinterpret_cast<float (*)[DIN_]>(sh);
        for (int i = tid; i < BT * DIN_; i += NTHREADS) {
            int bb = i >> 9;
            int d  = i & (DIN_ - 1);
            sx[bb][d] = x_t[(b0 + bb) * DIN_ + d];
        }
        __syncthreads();

        float acc1[BT] = {0.f, 0.f, 0.f, 0.f};
        float acc2[BT] = {0.f, 0.f, 0.f, 0.f};
#pragma unroll 8
        for (int d = 0; d < DIN_; d++) {
            float w1 = wx1[d * HH_ + h];
            float w2 = wx2[d * HH_ + h];
#pragma unroll
            for (int bb = 0; bb < BT; bb++) {
                float xv = sx[bb][d];
                acc1[bb] = fmaf(xv, w1, acc1[bb]);
                acc2[bb] = fmaf(xv, w2, acc2[bb]);
            }
        }

        float exp_r = expf(r_param[h]);
        float r     = expf(-exp_r);
        float theta = expf(theta_param[h]);
        float g     = r * cosf(theta);
        float phi   = r * sinf(theta);
        float rr    = r * r;
        float nrm   = sqrtf(1.0f - rr);
        float d_g_w_r       = -exp_r * g;
        float d_phi_w_r     = -exp_r * phi;
        float d_g_w_theta   = -theta * phi;
        float d_phi_w_theta =  theta * g;
        float d_norm_w_r    =  exp_r * rr / nrm;

#pragma unroll
        for (int bb = 0; bb < BT; bb++) {
            int idx = (b0 + bb) * HH_ + h;
            float hc1 = h_c1[idx];
            float hc2 = h_c2[idx];
            float m0 = gm0[idx], m1 = gm1[idx], m2 = gm2[idx], m3 = gm3[idx];
            float w1x = acc1[bb];
            float w2x = acc2[bb];

            out[0 * SZ_SMALL + idx] = g * hc1 - phi * hc2 + nrm * w1x;
            out[1 * SZ_SMALL + idx] = g * hc2 + phi * hc1 + nrm * w2x;
            out[2 * SZ_SMALL + idx] = d_g_w_r * hc1 + g * m0 - d_phi_w_r * hc2 - phi * m1 + d_norm_w_r * w1x;
            out[3 * SZ_SMALL + idx] = d_g_w_r * hc2 + g * m1 + d_phi_w_r * hc1 + phi * m0 + d_norm_w_r * w2x;
            out[4 * SZ_SMALL + idx] = d_g_w_theta * hc1 + g * m2 - d_phi_w_theta * hc2 - phi * m3;
            out[5 * SZ_SMALL + idx] = d_g_w_theta * hc2 + g * m3 + d_phi_w_theta * hc1 + phi * m2;
        }
    }

    // ================= streaming: per-thread h scalars (registers) ==========
    const int h0 = (tid & 127) << 2;
    float4 gv, pv, nv;
    {
        float tg[4], tp_[4], tn[4];
#pragma unroll
        for (int k = 0; k < 4; k++) {
            float exp_r = expf(r_param[h0 + k]);
            float r     = expf(-exp_r);
            float theta = expf(theta_param[h0 + k]);
            tg[k]  = r * cosf(theta);
            tp_[k] = r * sinf(theta);
            tn[k]  = sqrtf(1.0f - r * r);
        }
        gv = make_float4(tg[0],  tg[1],  tg[2],  tg[3]);
        pv = make_float4(tp_[0], tp_[1], tp_[2], tp_[3]);
        nv = make_float4(tn[0],  tn[1],  tn[2],  tn[3]);
    }

    float4* outBig = reinterpret_cast<float4*>(out + SMALL);

    // ================= dynamic chunk-stealing loop ==========================
    for (;;) {
        if (tid == 0) s_chunk = atomicAdd(&g_ctr, 1);
        __syncthreads();
        const int c = s_chunk;
        if (c >= NCHUNK) break;

        const int   half = c & 1;
        const int   base = (c >> 1) * CHUNK_V + tid;
        const float4* A  = half ? gm6 : gm4;
        const float4* B  = half ? gm7 : gm5;
        float4* OA = outBig + (size_t)(half ? 2 : 0) * (SZ_BIG / 4);
        float4* OB = outBig + (size_t)(half ? 3 : 1) * (SZ_BIG / 4);
        const float selA = half ? 0.f : 1.f;   // n4 gets +norm*x
        const float selB = half ? 1.f : 0.f;   // n7 gets +norm*x

        // 8 slices per chunk; 2 passes of 4 slices with all 8 loads
        // front-batched per pass (8 LDG.128 in flight per thread).
#pragma unroll
        for (int pass = 0; pass < 2; pass++) {
            const int vb = base + pass * 4 * NTHREADS;
            float4 a[4], b[4];
#pragma unroll
            for (int s = 0; s < 4; s++) {
                a[s] = __ldcs(A + (vb + s * NTHREADS));
                b[s] = __ldcs(B + (vb + s * NTHREADS));
            }
#pragma unroll
            for (int s = 0; s < 4; s++) {
                const int v = vb + s * NTHREADS;
                float x  = __ldg(x_t + (v >> 7));
                float xa = selA * x, xb = selB * x;

                float4 oa, ob;
                oa.x = gv.x * a[s].x - pv.x * b[s].x + nv.x * xa;
                oa.y = gv.y * a[s].y - pv.y * b[s].y + nv.y * xa;
                oa.z = gv.z * a[s].z - pv.z * b[s].z + nv.z * xa;
                oa.w = gv.w * a[s].w - pv.w * b[s].w + nv.w * xa;
                ob.x = gv.x * b[s].x + pv.x * a[s].x + nv.x * xb;
                ob.y = gv.y * b[s].y + pv.y * a[s].y + nv.y * xb;
                ob.z = gv.z * b[s].z + pv.z * a[s].z + nv.z * xb;
                ob.w = gv.w * b[s].w + pv.w * a[s].w + nv.w * xb;
                __stcs(OA + v, oa);
                __stcs(OB + v, ob);
            }
        }
        __syncthreads();   // protect s_chunk rewrite
    }

    // ================= counter reset (deterministic across replays) =========
    if (tid == 0) {
        __threadfence();
        int d = atomicAdd(&g_done, 1);
        if (d == (int)gridDim.x - 1) {
            g_ctr  = 0;
            g_done = 0;
            __threadfence();
        }
    }
}

extern "C" void kernel_launch(void* const* d_in, const int* in_sizes, int n_in,
                              void* d_out, int out_size) {
    const float* x_t   = (const float*)d_in[0];
    const float* h_c1  = (const float*)d_in[1];
    const float* h_c2  = (const float*)d_in[2];
    const float* gm0   = (const float*)d_in[3];
    const float* gm1   = (const float*)d_in[4];
    const float* gm2   = (const float*)d_in[5];
    const float* gm3   = (const float*)d_in[6];
    const float* gm4   = (const float*)d_in[7];
    const float* gm5   = (const float*)d_in[8];
    const float* gm6   = (const float*)d_in[9];
    const float* gm7   = (const float*)d_in[10];
    const float* r_p   = (const float*)d_in[11];
    const float* th_p  = (const float*)d_in[12];
    const float* wx1   = (const float*)d_in[13];
    const float* wx2   = (const float*)d_in[14];
    float* out = (float*)d_out;

    fused_kernel<<<TOTAL_BLOCKS, NTHREADS>>>(
        x_t, h_c1, h_c2, gm0, gm1, gm2, gm3,
        (const float4*)gm4, (const float4*)gm5,
        (const float4*)gm6, (const float4*)gm7,
        r_p, th_p, wx1, wx2, out);
}

// round 6
// speedup vs baseline: 1.0415x; 1.0415x over previous
#include <cuda_runtime.h>

#define BB_   64
#define DIN_  512
#define HH_   512

#define GEMM_BLOCKS  32
#define TOTAL_BLOCKS 740        // 148 SMs * 5 blocks -> single wave
#define NTHREADS     256

#define CHUNK_V      1024       // float4 per chunk (8 * 128 h-vectors)
#define NV           (BB_ * DIN_ * HH_ / 4)       // 4,194,304 float4 per tensor
#define NCHUNK       (2 * (NV / CHUNK_V))         // 8192 chunks (2 halves)

__device__ int g_ctr  = 0;
__device__ int g_done = 0;

__global__ void __launch_bounds__(NTHREADS, 5)
fused_kernel(const float* __restrict__ x_t,
             const float* __restrict__ h_c1,
             const float* __restrict__ h_c2,
             const float* __restrict__ gm0,
             const float* __restrict__ gm1,
             const float* __restrict__ gm2,
             const float* __restrict__ gm3,
             const float4* __restrict__ gm4,
             const float4* __restrict__ gm5,
             const float4* __restrict__ gm6,
             const float4* __restrict__ gm7,
             const float* __restrict__ r_param,
             const float* __restrict__ theta_param,
             const float* __restrict__ wx1,
             const float* __restrict__ wx2,
             float* __restrict__ out) {
    __shared__ __align__(16) float sh[4 * DIN_];   // GEMM staging
    __shared__ int s_chunk;

    const int tid = threadIdx.x;
    const int SZ_SMALL = BB_ * HH_;            // 32768
    const int SMALL    = 6 * SZ_SMALL;         // 196608 floats
    const int SZ_BIG   = BB_ * DIN_ * HH_;     // 16777216 floats

    // ================= GEMM + small epilogue (blocks 0..31) =================
    if (blockIdx.x < GEMM_BLOCKS) {
        const int BT = 4;
        const int bt = blockIdx.x >> 1;
        const int ht = blockIdx.x & 1;
        const int b0 = bt * BT;
        const int h  = ht * 256 + tid;

        float (*sx)[DIN_] = reinterpret_cast<float (*)[DIN_]>(sh);
        for (int i = tid; i < BT * DIN_; i += NTHREADS) {
            int bb = i >> 9;
            int d  = i & (DIN_ - 1);
            sx[bb][d] = x_t[(b0 + bb) * DIN_ + d];
        }
        __syncthreads();

        float acc1[BT] = {0.f, 0.f, 0.f, 0.f};
        float acc2[BT] = {0.f, 0.f, 0.f, 0.f};
#pragma unroll 8
        for (int d = 0; d < DIN_; d++) {
            float w1 = wx1[d * HH_ + h];
            float w2 = wx2[d * HH_ + h];
#pragma unroll
            for (int bb = 0; bb < BT; bb++) {
                float xv = sx[bb][d];
                acc1[bb] = fmaf(xv, w1, acc1[bb]);
                acc2[bb] = fmaf(xv, w2, acc2[bb]);
            }
        }

        float exp_r = expf(r_param[h]);
        float r     = expf(-exp_r);
        float theta = expf(theta_param[h]);
        float g     = r * cosf(theta);
        float phi   = r * sinf(theta);
        float rr    = r * r;
        float nrm   = sqrtf(1.0f - rr);
        float d_g_w_r       = -exp_r * g;
        float d_phi_w_r     = -exp_r * phi;
        float d_g_w_theta   = -theta * phi;
        float d_phi_w_theta =  theta * g;
        float d_norm_w_r    =  exp_r * rr / nrm;

#pragma unroll
        for (int bb = 0; bb < BT; bb++) {
            int idx = (b0 + bb) * HH_ + h;
            float hc1 = h_c1[idx];
            float hc2 = h_c2[idx];
            float m0 = gm0[idx], m1 = gm1[idx], m2 = gm2[idx], m3 = gm3[idx];
            float w1x = acc1[bb];
            float w2x = acc2[bb];

            out[0 * SZ_SMALL + idx] = g * hc1 - phi * hc2 + nrm * w1x;
            out[1 * SZ_SMALL + idx] = g * hc2 + phi * hc1 + nrm * w2x;
            out[2 * SZ_SMALL + idx] = d_g_w_r * hc1 + g * m0 - d_phi_w_r * hc2 - phi * m1 + d_norm_w_r * w1x;
            out[3 * SZ_SMALL + idx] = d_g_w_r * hc2 + g * m1 + d_phi_w_r * hc1 + phi * m0 + d_norm_w_r * w2x;
            out[4 * SZ_SMALL + idx] = d_g_w_theta * hc1 + g * m2 - d_phi_w_theta * hc2 - phi * m3;
            out[5 * SZ_SMALL + idx] = d_g_w_theta * hc2 + g * m3 + d_phi_w_theta * hc1 + phi * m2;
        }
    }

    // ================= streaming: per-thread h scalars (registers) ==========
    // chunk base is 1024-aligned (multiple of 128) -> h vector index == tid&127
    const int h0 = (tid & 127) << 2;
    float4 gv, pv, nv;
    {
        float tg[4], tp_[4], tn[4];
#pragma unroll
        for (int k = 0; k < 4; k++) {
            float exp_r = expf(r_param[h0 + k]);
            float r     = expf(-exp_r);
            float theta = expf(theta_param[h0 + k]);
            tg[k]  = r * cosf(theta);
            tp_[k] = r * sinf(theta);
            tn[k]  = sqrtf(1.0f - r * r);
        }
        gv = make_float4(tg[0],  tg[1],  tg[2],  tg[3]);
        pv = make_float4(tp_[0], tp_[1], tp_[2], tp_[3]);
        nv = make_float4(tn[0],  tn[1],  tn[2],  tn[3]);
    }

    float4* outBig = reinterpret_cast<float4*>(out + SMALL);

    // ================= dynamic chunk-stealing loop ==========================
    for (;;) {
        if (tid == 0) s_chunk = atomicAdd(&g_ctr, 1);
        __syncthreads();
        const int c = s_chunk;
        if (c >= NCHUNK) break;

        const int   half = c & 1;
        const int   base = (c >> 1) * CHUNK_V + tid;
        const float4* A  = half ? gm6 : gm4;
        const float4* B  = half ? gm7 : gm5;
        float4* OA = outBig + (size_t)(half ? 2 : 0) * (SZ_BIG / 4);
        float4* OB = outBig + (size_t)(half ? 3 : 1) * (SZ_BIG / 4);
        const float selA = half ? 0.f : 1.f;   // n4 gets +norm*x
        const float selB = half ? 1.f : 0.f;   // n7 gets +norm*x

        // 4 slices per chunk; 2 passes of 2 slices, all loads (incl. x_t)
        // front-batched per pass.
#pragma unroll
        for (int j = 0; j < 4; j += 2) {
            const int v0 = base + j * NTHREADS;
            const int v1 = v0 + NTHREADS;
            float4 a0 = __ldcs(A + v0);
            float4 b0 = __ldcs(B + v0);
            float4 a1 = __ldcs(A + v1);
            float4 b1 = __ldcs(B + v1);
            float x0 = __ldg(x_t + (v0 >> 7));
            float x1 = __ldg(x_t + (v1 >> 7));
            float xa0 = selA * x0, xb0 = selB * x0;
            float xa1 = selA * x1, xb1 = selB * x1;

            float4 oa, ob;
            oa.x = gv.x * a0.x - pv.x * b0.x + nv.x * xa0;
            oa.y = gv.y * a0.y - pv.y * b0.y + nv.y * xa0;
            oa.z = gv.z * a0.z - pv.z * b0.z + nv.z * xa0;
            oa.w = gv.w * a0.w - pv.w * b0.w + nv.w * xa0;
            ob.x = gv.x * b0.x + pv.x * a0.x + nv.x * xb0;
            ob.y = gv.y * b0.y + pv.y * a0.y + nv.y * xb0;
            ob.z = gv.z * b0.z + pv.z * a0.z + nv.z * xb0;
            ob.w = gv.w * b0.w + pv.w * a0.w + nv.w * xb0;
            __stcs(OA + v0, oa);
            __stcs(OB + v0, ob);

            oa.x = gv.x * a1.x - pv.x * b1.x + nv.x * xa1;
            oa.y = gv.y * a1.y - pv.y * b1.y + nv.y * xa1;
            oa.z = gv.z * a1.z - pv.z * b1.z + nv.z * xa1;
            oa.w = gv.w * a1.w - pv.w * b1.w + nv.w * xa1;
            ob.x = gv.x * b1.x + pv.x * a1.x + nv.x * xb1;
            ob.y = gv.y * b1.y + pv.y * a1.y + nv.y * xb1;
            ob.z = gv.z * b1.z + pv.z * a1.z + nv.z * xb1;
            ob.w = gv.w * b1.w + pv.w * a1.w + nv.w * xb1;
            __stcs(OA + v1, oa);
            __stcs(OB + v1, ob);
        }
        __syncthreads();   // protect s_chunk rewrite
    }

    // ================= counter reset (deterministic across replays) =========
    if (tid == 0) {
        __threadfence();
        int d = atomicAdd(&g_done, 1);
        if (d == (int)gridDim.x - 1) {
            g_ctr  = 0;
            g_done = 0;
            __threadfence();
        }
    }
}

extern "C" void kernel_launch(void* const* d_in, const int* in_sizes, int n_in,
                              void* d_out, int out_size) {
    const float* x_t   = (const float*)d_in[0];
    const float* h_c1  = (const float*)d_in[1];
    const float* h_c2  = (const float*)d_in[2];
    const float* gm0   = (const float*)d_in[3];
    const float* gm1   = (const float*)d_in[4];
    const float* gm2   = (const float*)d_in[5];
    const float* gm3   = (const float*)d_in[6];
    const float* gm4   = (const float*)d_in[7];
    const float* gm5   = (const float*)d_in[8];
    const float* gm6   = (const float*)d_in[9];
    const float* gm7   = (const float*)d_in[10];
    const float* r_p   = (const float*)d_in[11];
    const float* th_p  = (const float*)d_in[12];
    const float* wx1   = (const float*)d_in[13];
    const float* wx2   = (const float*)d_in[14];
    float* out = (float*)d_out;

    fused_kernel<<<TOTAL_BLOCKS, NTHREADS>>>(
        x_t, h_c1, h_c2, gm0, gm1, gm2, gm3,
        (const float4*)gm4, (const float4*)gm5,
        (const float4*)gm6, (const float4*)gm7,
        r_p, th_p, wx1, wx2, out);
}